// round 1
// baseline (speedup 1.0000x reference)
#include <cuda_runtime.h>
#include <cuda_bf16.h>
#include <mma.h>

using namespace nvcuda;

#define BB   128
#define NN   36
#define FEATD 2048
#define MIDD 517
#define HIDD 128
#define OUTD 1024
#define G4   4096
#define KPAD 544          // 517 padded to multiple of 32
#define TSTEPS 36

// ------------------------- scratch (static device arrays) -------------------
__device__ float g_scale[BB];
__device__ float g_sigatt[BB * NN];
__device__ float g_feats[BB * MIDD * NN];          // 9.5 MB  [b][m][n]
__device__ float g_hx[BB * HIDD * NN];             // [b][h][n]
__device__ float g_hy[BB * HIDD * NN];
__device__ float g_xseq[(size_t)TSTEPS * BB * KPAD];   // [t][b][c] padded
__device__ float g_wih_pad[(size_t)G4 * KPAD];         // [row][c] padded
__device__ float g_gates_in[(size_t)TSTEPS * BB * G4]; // 75.5 MB
__device__ float g_gates[BB * G4];
__device__ float g_h[BB * OUTD];
__device__ float g_c[BB * OUTD];

// ------------------------- tiny prep kernels --------------------------------
__global__ void k_scale(const float* __restrict__ boxes) {
    int b = blockIdx.x * blockDim.x + threadIdx.x;
    if (b >= BB) return;
    const float* p = boxes + (size_t)b * 4 * NN;
    float m = -1e30f;
    for (int i = 0; i < 4 * NN; i++) m = fmaxf(m, p[i]);
    g_scale[b] = m;
}

__global__ void k_head(const float* __restrict__ boxes,
                       const float* __restrict__ att) {
    int idx = blockIdx.x * blockDim.x + threadIdx.x;
    if (idx >= BB * NN) return;
    int b = idx / NN, n = idx - b * NN;
    float inv = 1.f / g_scale[b];
    for (int r = 0; r < 4; r++)
        g_feats[(size_t)b * MIDD * NN + r * NN + n] =
            boxes[(size_t)b * 4 * NN + r * NN + n] * inv;
    float a = att[idx];
    g_feats[(size_t)b * MIDD * NN + 4 * NN + n] = a;
    g_sigatt[idx] = 1.f / (1.f + expf(-a));
}

__global__ void k_pad_wih(const float* __restrict__ wih) {
    int idx = blockIdx.x * blockDim.x + threadIdx.x;
    if (idx >= G4 * KPAD) return;
    int r = idx / KPAD, c = idx - r * KPAD;
    g_wih_pad[idx] = (c < MIDD) ? wih[(size_t)r * MIDD + c] : 0.f;
}

__global__ void k_init() {
    int idx = blockIdx.x * blockDim.x + threadIdx.x;
    if (idx >= BB * OUTD) return;
    g_h[idx] = 0.f;
    g_c[idx] = 0.f;
}

// ------------------------- WMMA TF32 64x64 tile core ------------------------
// C(64x64) = A[m0:m0+64, :K] * B[n0:n0+64, :K]^T   (both K-contiguous, NT)
// Returns pointer to shared 64x64 fp32 result (row-major, ld=64).
__device__ __forceinline__ float* gemm_tile_64x64_tf32(
    const float* __restrict__ A, const float* __restrict__ B,
    int lda, int ldb, int K, int m0, int n0)
{
    constexpr int LD = 36;  // 32 + 4 pad, keeps float4 stores 16B-aligned
    __shared__ float As[64 * LD];
    __shared__ float Bs[64 * LD];
    __shared__ float Cs[64 * 64];

    const int t = threadIdx.x;
    const int warpId = t >> 5;
    const int wm = warpId >> 1, wn = warpId & 1;

    wmma::fragment<wmma::accumulator, 16, 16, 8, float> acc[2][2];
#pragma unroll
    for (int i = 0; i < 2; i++)
#pragma unroll
        for (int j = 0; j < 2; j++) wmma::fill_fragment(acc[i][j], 0.0f);

    for (int k0 = 0; k0 < K; k0 += 32) {
#pragma unroll
        for (int c = 0; c < 4; c++) {
            int cid = t + c * 128;
            int row = cid >> 3, seg = (cid & 7) << 2;
            *(float4*)&As[row * LD + seg] =
                *(const float4*)&A[(size_t)(m0 + row) * lda + k0 + seg];
            *(float4*)&Bs[row * LD + seg] =
                *(const float4*)&B[(size_t)(n0 + row) * ldb + k0 + seg];
        }
        __syncthreads();
#pragma unroll
        for (int kk = 0; kk < 32; kk += 8) {
            wmma::fragment<wmma::matrix_a, 16, 16, 8, wmma::precision::tf32,
                           wmma::row_major> af[2];
            wmma::fragment<wmma::matrix_b, 16, 16, 8, wmma::precision::tf32,
                           wmma::col_major> bf[2];
#pragma unroll
            for (int i = 0; i < 2; i++) {
                wmma::load_matrix_sync(af[i], &As[(wm * 32 + i * 16) * LD + kk], LD);
#pragma unroll
                for (int e = 0; e < af[i].num_elements; e++)
                    af[i].x[e] = wmma::__float_to_tf32(af[i].x[e]);
                wmma::load_matrix_sync(bf[i], &Bs[(wn * 32 + i * 16) * LD + kk], LD);
#pragma unroll
                for (int e = 0; e < bf[i].num_elements; e++)
                    bf[i].x[e] = wmma::__float_to_tf32(bf[i].x[e]);
            }
#pragma unroll
            for (int i = 0; i < 2; i++)
#pragma unroll
                for (int j = 0; j < 2; j++)
                    wmma::mma_sync(acc[i][j], af[i], bf[j], acc[i][j]);
        }
        __syncthreads();
    }
#pragma unroll
    for (int i = 0; i < 2; i++)
#pragma unroll
        for (int j = 0; j < 2; j++)
            wmma::store_matrix_sync(&Cs[(wm * 32 + i * 16) * 64 + wn * 32 + j * 16],
                                    acc[i][j], 64, wmma::mem_row_major);
    __syncthreads();
    return Cs;
}

// ------------------------- conv GEMM: f rows of feats -----------------------
// A=conv_w (512x2048), B=features (4608x2048), out -> feats[b][5+m][n] + bias
__global__ __launch_bounds__(128) void k_conv(const float* __restrict__ convw,
                                              const float* __restrict__ feat,
                                              const float* __restrict__ convb) {
    int m0 = blockIdx.x * 64, n0 = blockIdx.y * 64;
    float* Cs = gemm_tile_64x64_tf32(convw, feat, FEATD, FEATD, FEATD, m0, n0);
    for (int idx = threadIdx.x; idx < 64 * 64; idx += 128) {
        int r = idx >> 6, cc = idx & 63;
        int m = m0 + r, col = n0 + cc;
        int b = col / NN, n = col - b * NN;
        g_feats[(size_t)b * MIDD * NN + (5 + m) * NN + n] = Cs[idx] + convb[m];
    }
}

// ------------------------- skew hx/hy ---------------------------------------
__global__ __launch_bounds__(256) void k_skew(const float* __restrict__ wx,
                                              const float* __restrict__ wy) {
    int b = blockIdx.x;
    int t = threadIdx.x;
    int h = t & 127, pr = t >> 7;         // pr selects n-range [pr*18, pr*18+18)
    __shared__ float sf[32 * NN];
    __shared__ float swx[128 * 33];
    __shared__ float swy[128 * 33];
    float ax[18], ay[18];
#pragma unroll
    for (int n = 0; n < 18; n++) { ax[n] = 0.f; ay[n] = 0.f; }
    const float* fb = g_feats + (size_t)b * MIDD * NN;

    for (int mc = 0; mc < MIDD; mc += 32) {
        int mlen = min(32, MIDD - mc);
        for (int i = t; i < mlen * NN; i += 256) sf[i] = fb[mc * NN + i];
        if (pr == 0) {
            for (int j = 0; j < mlen; j++) swx[h * 33 + j] = wx[(size_t)h * MIDD + mc + j];
        } else {
            for (int j = 0; j < mlen; j++) swy[h * 33 + j] = wy[(size_t)h * MIDD + mc + j];
        }
        __syncthreads();
        for (int j = 0; j < mlen; j++) {
            float wxv = swx[h * 33 + j], wyv = swy[h * 33 + j];
            const float* sr = sf + j * NN + pr * 18;
#pragma unroll
            for (int n = 0; n < 18; n++) {
                float fv = sr[n];
                ax[n] += wxv * fv;
                ay[n] += wyv * fv;
            }
        }
        __syncthreads();
    }
#pragma unroll
    for (int n = 0; n < 18; n++) {
        g_hx[(size_t)b * HIDD * NN + h * NN + pr * 18 + n] = ax[n];
        g_hy[(size_t)b * HIDD * NN + h * NN + pr * 18 + n] = ay[n];
    }
}

// ------------------------- assignment + permutation mix ---------------------
__global__ __launch_bounds__(512) void k_assign(const float* __restrict__ b1,
                                                const float* __restrict__ w2,
                                                const float* __restrict__ b2p,
                                                const float* __restrict__ lrp) {
    int b = blockIdx.x, t = threadIdx.x;
    __shared__ float outS[1296], CSh[1296], LG[1296], PS[1296], DS[1296];
    __shared__ float saS[36], w2S[128], b1S[128];
    if (t < 128) { w2S[t] = w2[t]; b1S[t] = b1[t]; }
    if (t < 36) saS[t] = g_sigatt[b * NN + t];
    __syncthreads();

    const float* hxb = g_hx + (size_t)b * HIDD * NN;
    const float* hyb = g_hy + (size_t)b * HIDD * NN;
    float b2v = b2p[0];

    for (int p = t; p < 1296; p += 512) {
        int i = p / 36, j = p - i * 36;
        float s = 0.f;
#pragma unroll 8
        for (int h = 0; h < HIDD; h++) {
            float v = hxb[h * NN + i] + hyb[h * NN + j] + b1S[h];
            s += w2S[h] * fmaxf(v, 0.f);
        }
        outS[p] = s + b2v;
    }
    __syncthreads();
    for (int p = t; p < 1296; p += 512) {
        int i = p / 36, j = p - i * 36;
        CSh[p] = outS[p] - outS[j * 36 + i];
        LG[p] = 0.f;
    }
    __syncthreads();

    float lrabs = fabsf(lrp[0]);
    for (int it = 0; it < 3; it++) {
        if (t < 36) {
            float mx = -1e30f;
            for (int j = 0; j < 36; j++) mx = fmaxf(mx, LG[t * 36 + j]);
            float sum = 0.f;
            for (int j = 0; j < 36; j++) {
                float e = expf(LG[t * 36 + j] - mx);
                PS[t * 36 + j] = e;
                sum += e;
            }
            float inv = 1.f / sum;
            for (int j = 0; j < 36; j++) PS[t * 36 + j] *= inv;
        }
        __syncthreads();
        if (t < 36) {
            int l = t;
            float tot = 0.f;
            for (int i = 0; i < 36; i++) tot += PS[i * 36 + l];
            float run = 0.f;
            for (int i = 0; i < 36; i++) {
                float p = PS[i * 36 + l];
                run += p;
                DS[i * 36 + l] = tot - 2.f * run + p;  // above - below
            }
        }
        __syncthreads();
        for (int p = t; p < 1296; p += 512) {
            int i = p / 36, j = p - i * 36;
            float gsum = 0.f;
#pragma unroll
            for (int l = 0; l < 36; l++) gsum += DS[i * 36 + l] * CSh[j * 36 + l];
            LG[p] -= lrabs * gsum;
        }
        __syncthreads();
    }
    // final A = softmax(logits) rows -> PS
    if (t < 36) {
        float mx = -1e30f;
        for (int j = 0; j < 36; j++) mx = fmaxf(mx, LG[t * 36 + j]);
        float sum = 0.f;
        for (int j = 0; j < 36; j++) {
            float e = expf(LG[t * 36 + j] - mx);
            PS[t * 36 + j] = e;
            sum += e;
        }
        float inv = 1.f / sum;
        for (int j = 0; j < 36; j++) PS[t * 36 + j] *= inv;
    }
    __syncthreads();

    // x_seq[i][b][c] = sum_l feats[b,c,l]*sigmoid(att[b,l])*A[i,l]
    const float* fb = g_feats + (size_t)b * MIDD * NN;
    for (int p = t; p < MIDD * NN; p += 512) {
        int c = p / 36, i = p - c * 36;
        float s = 0.f;
#pragma unroll
        for (int l = 0; l < 36; l++) s += fb[c * 36 + l] * saS[l] * PS[i * 36 + l];
        g_xseq[(size_t)i * BB * KPAD + (size_t)b * KPAD + c] = s;
    }
    for (int p = t; p < (KPAD - MIDD) * NN; p += 512) {
        int c = MIDD + p / 36, i = p - (p / 36) * 36;
        g_xseq[(size_t)i * BB * KPAD + (size_t)b * KPAD + c] = 0.f;
    }
}

// ------------------------- input-gate GEMM ----------------------------------
// A=g_xseq (4608 x 544), B=g_wih_pad (4096 x 544) -> gates_in + bias
__global__ __launch_bounds__(128) void k_gin(const float* __restrict__ bih,
                                             const float* __restrict__ bhh) {
    int m0 = blockIdx.x * 64, n0 = blockIdx.y * 64;
    float* Cs = gemm_tile_64x64_tf32(g_xseq, g_wih_pad, KPAD, KPAD, KPAD, m0, n0);
    for (int idx = threadIdx.x; idx < 64 * 64; idx += 128) {
        int r = idx >> 6, cc = idx & 63;
        int row = m0 + r, col = n0 + cc;
        g_gates_in[(size_t)row * G4 + col] = Cs[idx] + bih[col] + bhh[col];
    }
}

// ------------------------- recurrent step GEMM ------------------------------
__global__ __launch_bounds__(128) void k_stepgemm(const float* __restrict__ whh,
                                                  int s) {
    int m0 = blockIdx.x * 64, n0 = blockIdx.y * 64;
    float* Cs = gemm_tile_64x64_tf32(g_h, whh, OUTD, OUTD, OUTD, m0, n0);
    const float* gin = g_gates_in + (size_t)s * BB * G4;
    for (int idx = threadIdx.x; idx < 64 * 64; idx += 128) {
        int r = idx >> 6, cc = idx & 63;
        int row = m0 + r, col = n0 + cc;
        g_gates[(size_t)row * G4 + col] = Cs[idx] + gin[(size_t)row * G4 + col];
    }
}

// ------------------------- LSTM pointwise update ----------------------------
__global__ void k_update(float* __restrict__ out_c) {
    int idx = blockIdx.x * blockDim.x + threadIdx.x;
    if (idx >= BB * OUTD) return;
    int b = idx >> 10;
    int o = idx & 1023;
    const float* g = g_gates + (size_t)b * G4;
    float ig = g[o];
    float fg = g[o + OUTD];
    float gg = g[o + 2 * OUTD];
    float og = g[o + 3 * OUTD];
    float si = 1.f / (1.f + expf(-ig));
    float sf = 1.f / (1.f + expf(-fg));
    float so = 1.f / (1.f + expf(-og));
    float c = sf * g_c[idx] + si * tanhf(gg);
    g_c[idx] = c;
    g_h[idx] = so * tanhf(c);
    if (out_c) out_c[idx] = c;
}

// ------------------------- launch -------------------------------------------
extern "C" void kernel_launch(void* const* d_in, const int* in_sizes, int n_in,
                              void* d_out, int out_size) {
    const float* boxes     = (const float*)d_in[0];
    const float* attention = (const float*)d_in[1];
    const float* features  = (const float*)d_in[2];
    const float* conv_w    = (const float*)d_in[3];
    const float* conv_b    = (const float*)d_in[4];
    const float* skew_wx   = (const float*)d_in[5];
    const float* skew_wy   = (const float*)d_in[6];
    const float* skew_b1   = (const float*)d_in[7];
    const float* skew_w2   = (const float*)d_in[8];
    const float* skew_b2   = (const float*)d_in[9];
    const float* w_ih      = (const float*)d_in[10];
    const float* w_hh      = (const float*)d_in[11];
    const float* b_ih      = (const float*)d_in[12];
    const float* b_hh      = (const float*)d_in[13];
    const float* lr        = (const float*)d_in[14];

    k_scale<<<1, 128>>>(boxes);
    k_head<<<(BB * NN + 255) / 256, 256>>>(boxes, attention);
    k_pad_wih<<<(G4 * KPAD + 255) / 256, 256>>>(w_ih);
    k_init<<<(BB * OUTD + 255) / 256, 256>>>();

    k_conv<<<dim3(8, 72), 128>>>(conv_w, features, conv_b);
    k_skew<<<BB, 256>>>(skew_wx, skew_wy);
    k_assign<<<BB, 512>>>(skew_b1, skew_w2, skew_b2, lr);
    k_gin<<<dim3(72, 64), 128>>>(b_ih, b_hh);

    for (int s = 0; s < TSTEPS; s++) {
        k_stepgemm<<<dim3(2, 64), 128>>>(w_hh, s);
        k_update<<<(BB * OUTD + 255) / 256, 256>>>(
            s == TSTEPS - 1 ? (float*)d_out : nullptr);
    }
}

// round 2
// speedup vs baseline: 1.5833x; 1.5833x over previous
#include <cuda_runtime.h>
#include <cuda_bf16.h>
#include <mma.h>

using namespace nvcuda;
typedef __nv_bfloat16 bf16;

#define BB   128
#define NN   36
#define FEATD 2048
#define MIDD 517
#define HIDD 128
#define OUTD 1024
#define G4   4096
#define KPAD 544
#define TSTEPS 36
#define LDT 40          // smem row stride (bf16) for 32-wide k-chunk, +8 pad

// ------------------------- scratch -------------------------
__device__ float g_scale[BB];
__device__ float g_sigatt[BB * NN];
__device__ float g_feats[BB * MIDD * NN];                 // [b][m][n] fp32
__device__ float g_hx[BB * HIDD * NN];
__device__ float g_hy[BB * HIDD * NN];

__device__ bf16 g_feat_hi[(size_t)BB * NN * FEATD];       // [b*36+n][k]
__device__ bf16 g_feat_lo[(size_t)BB * NN * FEATD];
__device__ bf16 g_convw_hi[512 * FEATD];
__device__ bf16 g_convw_lo[512 * FEATD];
__device__ bf16 g_wih_hi[(size_t)G4 * KPAD];              // reordered col=u*4+g
__device__ bf16 g_wih_lo[(size_t)G4 * KPAD];
__device__ bf16 g_whh_hi[(size_t)G4 * OUTD];              // reordered
__device__ bf16 g_whh_lo[(size_t)G4 * OUTD];
__device__ bf16 g_xh[(size_t)TSTEPS * BB * KPAD];         // [t*128+b][k]
__device__ bf16 g_xl[(size_t)TSTEPS * BB * KPAD];
__device__ float g_gates_in[(size_t)TSTEPS * BB * G4];    // reordered cols
__device__ bf16 g_hhi0[BB * OUTD];
__device__ bf16 g_hlo0[BB * OUTD];
__device__ bf16 g_hhi1[BB * OUTD];
__device__ bf16 g_hlo1[BB * OUTD];
__device__ float g_c[BB * OUTD];

// ------------------------- helpers -------------------------
__device__ __forceinline__ void split_write(float v, bf16* hi, bf16* lo) {
    bf16 h = __float2bfloat16(v);
    *hi = h;
    *lo = __float2bfloat16(v - __bfloat162float(h));
}

__device__ __forceinline__ void cp16(void* dst, const void* src) {
    unsigned d = (unsigned)__cvta_generic_to_shared(dst);
    asm volatile("cp.async.ca.shared.global [%0], [%1], 16;\n" ::"r"(d), "l"(src));
}

// ------------------------- prep kernels -------------------------
__global__ void k_scale(const float* __restrict__ boxes) {
    int b = blockIdx.x * blockDim.x + threadIdx.x;
    if (b >= BB) return;
    const float* p = boxes + (size_t)b * 4 * NN;
    float m = -1e30f;
    for (int i = 0; i < 4 * NN; i++) m = fmaxf(m, p[i]);
    g_scale[b] = m;
}

__global__ void k_head(const float* __restrict__ boxes,
                       const float* __restrict__ att) {
    int idx = blockIdx.x * blockDim.x + threadIdx.x;
    if (idx >= BB * NN) return;
    int b = idx / NN, n = idx - b * NN;
    float inv = 1.f / g_scale[b];
    for (int r = 0; r < 4; r++)
        g_feats[(size_t)b * MIDD * NN + r * NN + n] =
            boxes[(size_t)b * 4 * NN + r * NN + n] * inv;
    float a = att[idx];
    g_feats[(size_t)b * MIDD * NN + 4 * NN + n] = a;
    g_sigatt[idx] = 1.f / (1.f + expf(-a));
}

__global__ void k_split_feat(const float* __restrict__ src) {
    size_t idx = (size_t)blockIdx.x * blockDim.x + threadIdx.x;
    if (idx >= (size_t)BB * NN * FEATD) return;
    split_write(src[idx], &g_feat_hi[idx], &g_feat_lo[idx]);
}

__global__ void k_split_convw(const float* __restrict__ src) {
    size_t idx = (size_t)blockIdx.x * blockDim.x + threadIdx.x;
    if (idx >= (size_t)512 * FEATD) return;
    split_write(src[idx], &g_convw_hi[idx], &g_convw_lo[idx]);
}

__global__ void k_split_wih(const float* __restrict__ wih) {
    size_t idx = (size_t)blockIdx.x * blockDim.x + threadIdx.x;
    if (idx >= (size_t)G4 * KPAD) return;
    int cr = (int)(idx / KPAD), k = (int)(idx - (size_t)cr * KPAD);
    int u = cr >> 2, g = cr & 3;
    float v = (k < MIDD) ? wih[(size_t)(g * OUTD + u) * MIDD + k] : 0.f;
    split_write(v, &g_wih_hi[idx], &g_wih_lo[idx]);
}

__global__ void k_split_whh(const float* __restrict__ whh) {
    size_t idx = (size_t)blockIdx.x * blockDim.x + threadIdx.x;
    if (idx >= (size_t)G4 * OUTD) return;
    int cr = (int)(idx / OUTD), k = (int)(idx - (size_t)cr * OUTD);
    int u = cr >> 2, g = cr & 3;
    float v = whh[(size_t)(g * OUTD + u) * OUTD + k];
    split_write(v, &g_whh_hi[idx], &g_whh_lo[idx]);
}

__global__ void k_init() {
    int idx = blockIdx.x * blockDim.x + threadIdx.x;
    if (idx >= BB * OUTD) return;
    g_hhi0[idx] = __float2bfloat16(0.f);
    g_hlo0[idx] = __float2bfloat16(0.f);
    g_c[idx] = 0.f;
}

// ------------------------- bf16x3 GEMM core (64x64 tile, 256 thr) ----------
// C = A[m0:+64, :K] * B[n0:+64, :K]^T, fp32 acc, ~fp32 precision via 3 terms.
__device__ __forceinline__ float* gemm_bf16x3(
    const bf16* __restrict__ Ahi, const bf16* __restrict__ Alo,
    const bf16* __restrict__ Bhi, const bf16* __restrict__ Blo,
    int lda, int ldb, int K, int m0, int n0)
{
    __shared__ __align__(16) unsigned char raw[40960];
    bf16* sb = (bf16*)raw;   // buffers: [buf][Ahi,Alo,Bhi,Blo] each 2560 elems

    const int t = threadIdx.x, w = t >> 5;
    const int wm = w >> 1, wn = w & 1;
    const int lrow = t >> 2, lse = (t & 3) * 8;

    wmma::fragment<wmma::accumulator, 16, 16, 16, float> acc[2];
    wmma::fill_fragment(acc[0], 0.f);
    wmma::fill_fragment(acc[1], 0.f);

    const int nch = K / 32;

    // prefetch chunk 0
    {
        bf16* base = sb;
        cp16(base + 0 * 2560 + lrow * LDT + lse, Ahi + (size_t)(m0 + lrow) * lda + lse);
        cp16(base + 1 * 2560 + lrow * LDT + lse, Alo + (size_t)(m0 + lrow) * lda + lse);
        cp16(base + 2 * 2560 + lrow * LDT + lse, Bhi + (size_t)(n0 + lrow) * ldb + lse);
        cp16(base + 3 * 2560 + lrow * LDT + lse, Blo + (size_t)(n0 + lrow) * ldb + lse);
        asm volatile("cp.async.commit_group;\n");
    }

    int buf = 0;
    for (int kc = 0; kc < nch; kc++) {
        if (kc + 1 < nch) {
            int k0 = (kc + 1) * 32;
            bf16* base = sb + (buf ^ 1) * 4 * 2560;
            cp16(base + 0 * 2560 + lrow * LDT + lse, Ahi + (size_t)(m0 + lrow) * lda + k0 + lse);
            cp16(base + 1 * 2560 + lrow * LDT + lse, Alo + (size_t)(m0 + lrow) * lda + k0 + lse);
            cp16(base + 2 * 2560 + lrow * LDT + lse, Bhi + (size_t)(n0 + lrow) * ldb + k0 + lse);
            cp16(base + 3 * 2560 + lrow * LDT + lse, Blo + (size_t)(n0 + lrow) * ldb + k0 + lse);
            asm volatile("cp.async.commit_group;\n");
            asm volatile("cp.async.wait_group 1;\n");
        } else {
            asm volatile("cp.async.wait_group 0;\n");
        }
        __syncthreads();

        bf16* base = sb + buf * 4 * 2560;
        bf16* sAhi = base;
        bf16* sAlo = base + 2560;
        bf16* sBhi = base + 2 * 2560;
        bf16* sBlo = base + 3 * 2560;
#pragma unroll
        for (int ks = 0; ks < 2; ks++) {
            const int kk = ks * 16;
            wmma::fragment<wmma::matrix_a, 16, 16, 16, bf16, wmma::row_major> ah, al;
            wmma::fragment<wmma::matrix_b, 16, 16, 16, bf16, wmma::col_major> bh0, bh1, bl0, bl1;
            wmma::load_matrix_sync(ah, &sAhi[(wm * 16) * LDT + kk], LDT);
            wmma::load_matrix_sync(al, &sAlo[(wm * 16) * LDT + kk], LDT);
            wmma::load_matrix_sync(bh0, &sBhi[(wn * 32) * LDT + kk], LDT);
            wmma::load_matrix_sync(bh1, &sBhi[(wn * 32 + 16) * LDT + kk], LDT);
            wmma::load_matrix_sync(bl0, &sBlo[(wn * 32) * LDT + kk], LDT);
            wmma::load_matrix_sync(bl1, &sBlo[(wn * 32 + 16) * LDT + kk], LDT);
            wmma::mma_sync(acc[0], ah, bh0, acc[0]);
            wmma::mma_sync(acc[1], ah, bh1, acc[1]);
            wmma::mma_sync(acc[0], ah, bl0, acc[0]);
            wmma::mma_sync(acc[1], ah, bl1, acc[1]);
            wmma::mma_sync(acc[0], al, bh0, acc[0]);
            wmma::mma_sync(acc[1], al, bh1, acc[1]);
        }
        __syncthreads();
        buf ^= 1;
    }

    float* Cs = (float*)raw;   // alias over load buffers (done with them)
    wmma::store_matrix_sync(&Cs[(wm * 16) * 64 + wn * 32], acc[0], 64, wmma::mem_row_major);
    wmma::store_matrix_sync(&Cs[(wm * 16) * 64 + wn * 32 + 16], acc[1], 64, wmma::mem_row_major);
    __syncthreads();
    return Cs;
}

// ------------------------- conv GEMM -------------------------
__global__ __launch_bounds__(256) void k_conv(const float* __restrict__ convb) {
    int m0 = blockIdx.x * 64, n0 = blockIdx.y * 64;
    float* Cs = gemm_bf16x3(g_convw_hi, g_convw_lo, g_feat_hi, g_feat_lo,
                            FEATD, FEATD, FEATD, m0, n0);
    for (int idx = threadIdx.x; idx < 64 * 64; idx += 256) {
        int r = idx >> 6, cc = idx & 63;
        int m = m0 + r, col = n0 + cc;
        int b = col / NN, n = col - b * NN;
        g_feats[(size_t)b * MIDD * NN + (5 + m) * NN + n] = Cs[idx] + convb[m];
    }
}

// ------------------------- skew hx/hy -------------------------
__global__ __launch_bounds__(256) void k_skew(const float* __restrict__ wx,
                                              const float* __restrict__ wy) {
    int b = blockIdx.x;
    int t = threadIdx.x;
    int h = t & 127, pr = t >> 7;
    __shared__ float sf[32 * NN];
    __shared__ float swx[128 * 33];
    __shared__ float swy[128 * 33];
    float ax[18], ay[18];
#pragma unroll
    for (int n = 0; n < 18; n++) { ax[n] = 0.f; ay[n] = 0.f; }
    const float* fb = g_feats + (size_t)b * MIDD * NN;

    for (int mc = 0; mc < MIDD; mc += 32) {
        int mlen = min(32, MIDD - mc);
        for (int i = t; i < mlen * NN; i += 256) sf[i] = fb[mc * NN + i];
        if (pr == 0) {
            for (int j = 0; j < mlen; j++) swx[h * 33 + j] = wx[(size_t)h * MIDD + mc + j];
        } else {
            for (int j = 0; j < mlen; j++) swy[h * 33 + j] = wy[(size_t)h * MIDD + mc + j];
        }
        __syncthreads();
        for (int j = 0; j < mlen; j++) {
            float wxv = swx[h * 33 + j], wyv = swy[h * 33 + j];
            const float* sr = sf + j * NN + pr * 18;
#pragma unroll
            for (int n = 0; n < 18; n++) {
                float fv = sr[n];
                ax[n] += wxv * fv;
                ay[n] += wyv * fv;
            }
        }
        __syncthreads();
    }
#pragma unroll
    for (int n = 0; n < 18; n++) {
        g_hx[(size_t)b * HIDD * NN + h * NN + pr * 18 + n] = ax[n];
        g_hy[(size_t)b * HIDD * NN + h * NN + pr * 18 + n] = ay[n];
    }
}

// ------------------------- assignment + permutation mix ---------------------
__global__ __launch_bounds__(512) void k_assign(const float* __restrict__ b1,
                                                const float* __restrict__ w2,
                                                const float* __restrict__ b2p,
                                                const float* __restrict__ lrp) {
    int b = blockIdx.x, t = threadIdx.x;
    __shared__ float outS[1296], CSh[1296], LG[1296], PS[1296], DS[1296];
    __shared__ float saS[36], w2S[128], b1S[128];
    if (t < 128) { w2S[t] = w2[t]; b1S[t] = b1[t]; }
    if (t < 36) saS[t] = g_sigatt[b * NN + t];
    __syncthreads();

    const float* hxb = g_hx + (size_t)b * HIDD * NN;
    const float* hyb = g_hy + (size_t)b * HIDD * NN;
    float b2v = b2p[0];

    for (int p = t; p < 1296; p += 512) {
        int i = p / 36, j = p - i * 36;
        float s = 0.f;
#pragma unroll 8
        for (int h = 0; h < HIDD; h++) {
            float v = hxb[h * NN + i] + hyb[h * NN + j] + b1S[h];
            s += w2S[h] * fmaxf(v, 0.f);
        }
        outS[p] = s + b2v;
    }
    __syncthreads();
    for (int p = t; p < 1296; p += 512) {
        int i = p / 36, j = p - i * 36;
        CSh[p] = outS[p] - outS[j * 36 + i];
        LG[p] = 0.f;
    }
    __syncthreads();

    float lrabs = fabsf(lrp[0]);
    for (int it = 0; it < 3; it++) {
        if (t < 36) {
            float mx = -1e30f;
            for (int j = 0; j < 36; j++) mx = fmaxf(mx, LG[t * 36 + j]);
            float sum = 0.f;
            for (int j = 0; j < 36; j++) {
                float e = expf(LG[t * 36 + j] - mx);
                PS[t * 36 + j] = e;
                sum += e;
            }
            float inv = 1.f / sum;
            for (int j = 0; j < 36; j++) PS[t * 36 + j] *= inv;
        }
        __syncthreads();
        if (t < 36) {
            int l = t;
            float tot = 0.f;
            for (int i = 0; i < 36; i++) tot += PS[i * 36 + l];
            float run = 0.f;
            for (int i = 0; i < 36; i++) {
                float p = PS[i * 36 + l];
                run += p;
                DS[i * 36 + l] = tot - 2.f * run + p;
            }
        }
        __syncthreads();
        for (int p = t; p < 1296; p += 512) {
            int i = p / 36, j = p - i * 36;
            float gsum = 0.f;
#pragma unroll
            for (int l = 0; l < 36; l++) gsum += DS[i * 36 + l] * CSh[j * 36 + l];
            LG[p] -= lrabs * gsum;
        }
        __syncthreads();
    }
    if (t < 36) {
        float mx = -1e30f;
        for (int j = 0; j < 36; j++) mx = fmaxf(mx, LG[t * 36 + j]);
        float sum = 0.f;
        for (int j = 0; j < 36; j++) {
            float e = expf(LG[t * 36 + j] - mx);
            PS[t * 36 + j] = e;
            sum += e;
        }
        float inv = 1.f / sum;
        for (int j = 0; j < 36; j++) PS[t * 36 + j] *= inv;
    }
    __syncthreads();

    // x_seq[i][b][c] = sum_l feats[b,c,l]*sig(att)*A[i,l]  -> split bf16
    const float* fb = g_feats + (size_t)b * MIDD * NN;
    for (int p = t; p < MIDD * NN; p += 512) {
        int c = p / 36, i = p - c * 36;
        float s = 0.f;
#pragma unroll
        for (int l = 0; l < 36; l++) s += fb[c * 36 + l] * saS[l] * PS[i * 36 + l];
        size_t di = ((size_t)i * BB + b) * KPAD + c;
        split_write(s, &g_xh[di], &g_xl[di]);
    }
    for (int p = t; p < (KPAD - MIDD) * NN; p += 512) {
        int c = MIDD + p / 36, i = p % 36;
        size_t di = ((size_t)i * BB + b) * KPAD + c;
        g_xh[di] = __float2bfloat16(0.f);
        g_xl[di] = __float2bfloat16(0.f);
    }
}

// ------------------------- input-gate GEMM (reordered cols) -----------------
__global__ __launch_bounds__(256) void k_gin(const float* __restrict__ bih,
                                             const float* __restrict__ bhh) {
    int m0 = blockIdx.x * 64, n0 = blockIdx.y * 64;
    float* Cs = gemm_bf16x3(g_xh, g_xl, g_wih_hi, g_wih_lo,
                            KPAD, KPAD, KPAD, m0, n0);
    for (int idx = threadIdx.x; idx < 64 * 64; idx += 256) {
        int r = idx >> 6, cc = idx & 63;
        int row = m0 + r, col = n0 + cc;
        int u = col >> 2, g = col & 3;
        int orig = g * OUTD + u;
        g_gates_in[(size_t)row * G4 + col] = Cs[idx] + bih[orig] + bhh[orig];
    }
}

// ------------------------- recurrent step GEMM + fused LSTM update ----------
__global__ __launch_bounds__(256) void k_step(int s, float* __restrict__ outc) {
    int m0 = blockIdx.x * 64, n0 = blockIdx.y * 64;
    const bf16* hin_hi = (s & 1) ? g_hhi1 : g_hhi0;
    const bf16* hin_lo = (s & 1) ? g_hlo1 : g_hlo0;
    bf16* hout_hi = (s & 1) ? g_hhi0 : g_hhi1;
    bf16* hout_lo = (s & 1) ? g_hlo0 : g_hlo1;

    float* Cs = gemm_bf16x3(hin_hi, hin_lo, g_whh_hi, g_whh_lo,
                            OUTD, OUTD, OUTD, m0, n0);

    const float* gin = g_gates_in + (size_t)s * BB * G4;
    for (int p = threadIdx.x; p < 1024; p += 256) {
        int r = p >> 4, lu = p & 15;
        int b = m0 + r;
        int u = (n0 >> 2) + lu;
        const float* gr = gin + (size_t)b * G4 + n0 + lu * 4;
        float* cr = &Cs[r * 64 + lu * 4];
        float ig = cr[0] + gr[0];
        float fg = cr[1] + gr[1];
        float gg = cr[2] + gr[2];
        float og = cr[3] + gr[3];
        float si = 1.f / (1.f + expf(-ig));
        float sf = 1.f / (1.f + expf(-fg));
        float so = 1.f / (1.f + expf(-og));
        int ci = b * OUTD + u;
        float c = sf * g_c[ci] + si * tanhf(gg);
        g_c[ci] = c;
        float h = so * tanhf(c);
        split_write(h, &hout_hi[ci], &hout_lo[ci]);
        if (outc) outc[ci] = c;
    }
}

// ------------------------- launch -------------------------
extern "C" void kernel_launch(void* const* d_in, const int* in_sizes, int n_in,
                              void* d_out, int out_size) {
    const float* boxes     = (const float*)d_in[0];
    const float* attention = (const float*)d_in[1];
    const float* features  = (const float*)d_in[2];
    const float* conv_w    = (const float*)d_in[3];
    const float* conv_b    = (const float*)d_in[4];
    const float* skew_wx   = (const float*)d_in[5];
    const float* skew_wy   = (const float*)d_in[6];
    const float* skew_b1   = (const float*)d_in[7];
    const float* skew_w2   = (const float*)d_in[8];
    const float* skew_b2   = (const float*)d_in[9];
    const float* w_ih      = (const float*)d_in[10];
    const float* w_hh      = (const float*)d_in[11];
    const float* b_ih      = (const float*)d_in[12];
    const float* b_hh      = (const float*)d_in[13];
    const float* lr        = (const float*)d_in[14];

    k_scale<<<1, 128>>>(boxes);
    k_head<<<(BB * NN + 255) / 256, 256>>>(boxes, attention);
    {
        size_t n = (size_t)BB * NN * FEATD;
        k_split_feat<<<(unsigned)((n + 511) / 512), 512>>>(features);
    }
    k_split_convw<<<(512 * FEATD + 511) / 512, 512>>>(conv_w);
    k_split_wih<<<(G4 * KPAD + 511) / 512, 512>>>(w_ih);
    k_split_whh<<<(G4 * OUTD + 511) / 512, 512>>>(w_hh);
    k_init<<<(BB * OUTD + 255) / 256, 256>>>();

    k_conv<<<dim3(8, 72), 256>>>(conv_b);
    k_skew<<<BB, 256>>>(skew_wx, skew_wy);
    k_assign<<<BB, 512>>>(skew_b1, skew_w2, skew_b2, lr);
    k_gin<<<dim3(72, 64), 256>>>(b_ih, b_hh);

    for (int s = 0; s < TSTEPS; s++) {
        k_step<<<dim3(2, 64), 256>>>(s, s == TSTEPS - 1 ? (float*)d_out : nullptr);
    }
}